// round 2
// baseline (speedup 1.0000x reference)
#include <cuda_runtime.h>

// ---------------------------------------------------------------------------
// ComputeAlignmentError on GB300.
// err[b,i,j] = || T_pred(i,j,:) - T_true(i,j,:) + 1e-8 ||_2 * mask[i]*mask[j]
// where T(i,j,k) = dot(coords[i] - origin[j], e_k[j]).
// Factorized: per-j constants (basis rows Ep, -Et, cc = eps - Ep.o_p + Et.o_t),
// per-i packed coords. Pair kernel: 21 FMA + 1 MUFU.SQRT per element.
// NOTE: mask arrives as int32 (bool promoted by harness) - read as const int*.
// ---------------------------------------------------------------------------

#define MAX_BN 8192
__device__ float4 g_jc[MAX_BN * 6];   // per-frame constants: Ep(9), -Et(9), cc(3), mask, pad
__device__ float4 g_ic[MAX_BN * 2];   // per-point coords: cp(3), mask | ct(3), 0

struct V3 { float x, y, z; };
__device__ __forceinline__ V3 v3(float x, float y, float z) { V3 v; v.x = x; v.y = y; v.z = z; return v; }
__device__ __forceinline__ V3 vsub(V3 a, V3 b) { return v3(a.x - b.x, a.y - b.y, a.z - b.z); }
__device__ __forceinline__ V3 vadd(V3 a, V3 b) { return v3(a.x + b.x, a.y + b.y, a.z + b.z); }
__device__ __forceinline__ float dot3(V3 a, V3 b) { return a.x * b.x + a.y * b.y + a.z * b.z; }
__device__ __forceinline__ V3 vnrm(V3 a) {
    // matches F.normalize: v / max(||v||, 1e-8)
    float nn = sqrtf(dot3(a, a));
    float inv = 1.0f / fmaxf(nn, 1e-8f);
    return v3(a.x * inv, a.y * inv, a.z * inv);
}
__device__ __forceinline__ V3 vcross(V3 a, V3 b) {
    return v3(a.y * b.z - a.z * b.y,
              a.z * b.x - a.x * b.z,
              a.x * b.y - a.y * b.x);
}

// frames layout: F[d][p] row-major (d = xyz coordinate axis-2, p = point index a/b/c axis-3)
__device__ __forceinline__ void frame_basis(const float* __restrict__ F,
                                            V3& o, V3& e1, V3& e2, V3& e3) {
    V3 a = v3(F[0], F[3], F[6]);
    V3 b = v3(F[1], F[4], F[7]);
    V3 c = v3(F[2], F[5], F[8]);
    V3 w1 = vnrm(vsub(a, b));
    V3 w2 = vnrm(vsub(c, b));
    e1 = vnrm(vadd(w1, w2));
    e2 = vnrm(vsub(w2, w1));
    e3 = vcross(e1, e2);
    o = b;
}

__global__ void precompute_kernel(const float* __restrict__ pc, const float* __restrict__ tc,
                                  const float* __restrict__ pf, const float* __restrict__ tf,
                                  const int* __restrict__ mask, int bn) {
    int t = blockIdx.x * blockDim.x + threadIdx.x;
    if (t >= bn) return;
    V3 op, p1, p2, p3, ot, t1, t2, t3;
    frame_basis(pf + (size_t)t * 9, op, p1, p2, p3);
    frame_basis(tf + (size_t)t * 9, ot, t1, t2, t3);
    float mf = (mask[t] != 0) ? 1.0f : 0.0f;
    const float eps = 1e-8f;  // pairwise_distance eps, folded into cc
    float cc0 = eps - dot3(p1, op) + dot3(t1, ot);
    float cc1 = eps - dot3(p2, op) + dot3(t2, ot);
    float cc2 = eps - dot3(p3, op) + dot3(t3, ot);
    float4* jp = g_jc + (size_t)t * 6;
    jp[0] = make_float4(p1.x,  p1.y,  p1.z,  p2.x);
    jp[1] = make_float4(p2.y,  p2.z,  p3.x,  p3.y);
    jp[2] = make_float4(p3.z, -t1.x, -t1.y, -t1.z);
    jp[3] = make_float4(-t2.x, -t2.y, -t2.z, -t3.x);
    jp[4] = make_float4(-t3.y, -t3.z,  cc0,  cc1);
    jp[5] = make_float4(cc2,   mf,    0.0f,  0.0f);
    const float* cpp = pc + (size_t)t * 3;
    const float* ctp = tc + (size_t)t * 3;
    g_ic[(size_t)t * 2 + 0] = make_float4(cpp[0], cpp[1], cpp[2], mf);
    g_ic[(size_t)t * 2 + 1] = make_float4(ctp[0], ctp[1], ctp[2], 0.0f);
}

#define JT 128   // j-tile = blockDim.x, lane-major -> coalesced stores
#define IT 128   // i-tile in shared memory

__global__ void __launch_bounds__(JT) pair_kernel(float* __restrict__ out, int n) {
    __shared__ float4 smI[IT * 2];
    int bb    = blockIdx.z;
    int j     = blockIdx.x * JT + threadIdx.x;
    int ibase = blockIdx.y * IT;
    int base  = bb * n;

    // stage i-tile coords into smem
    int nload = 2 * min(IT, n - ibase);
    for (int k = threadIdx.x; k < nload; k += JT)
        smI[k] = g_ic[(size_t)(base + ibase) * 2 + k];

    bool jok = j < n;
    const float4* jp = g_jc + (size_t)(base + (jok ? j : 0)) * 6;
    float4 q0 = jp[0], q1 = jp[1], q2 = jp[2], q3 = jp[3], q4 = jp[4], q5 = jp[5];
    float ep1x = q0.x, ep1y = q0.y, ep1z = q0.z;
    float ep2x = q0.w, ep2y = q1.x, ep2z = q1.y;
    float ep3x = q1.z, ep3y = q1.w, ep3z = q2.x;
    float mt1x = q2.y, mt1y = q2.z, mt1z = q2.w;
    float mt2x = q3.x, mt2y = q3.y, mt2z = q3.z;
    float mt3x = q3.w, mt3y = q4.x, mt3z = q4.y;
    float cc0  = q4.z, cc1  = q4.w, cc2  = q5.x, mj = q5.y;
    __syncthreads();

    int iend = min(IT, n - ibase);
    float* orow = out + (size_t)(base + ibase) * n + j;
    #pragma unroll 4
    for (int it = 0; it < iend; ++it) {
        float4 A  = smI[2 * it];       // cp.xyz, mask_i
        float4 Bv = smI[2 * it + 1];   // ct.xyz, 0
        float x0 = fmaf(ep1x, A.x, fmaf(ep1y, A.y, fmaf(ep1z, A.z,
                   fmaf(mt1x, Bv.x, fmaf(mt1y, Bv.y, fmaf(mt1z, Bv.z, cc0))))));
        float x1 = fmaf(ep2x, A.x, fmaf(ep2y, A.y, fmaf(ep2z, A.z,
                   fmaf(mt2x, Bv.x, fmaf(mt2y, Bv.y, fmaf(mt2z, Bv.z, cc1))))));
        float x2 = fmaf(ep3x, A.x, fmaf(ep3y, A.y, fmaf(ep3z, A.z,
                   fmaf(mt3x, Bv.x, fmaf(mt3y, Bv.y, fmaf(mt3z, Bv.z, cc2))))));
        float s = fmaf(x0, x0, fmaf(x1, x1, x2 * x2));
        float r;
        asm("sqrt.approx.f32 %0, %1;" : "=f"(r) : "f"(s));
        r *= A.w * mj;
        if (jok) orow[(size_t)it * n] = r;
    }
}

extern "C" void kernel_launch(void* const* d_in, const int* in_sizes, int n_in,
                              void* d_out, int out_size) {
    const float* pc = (const float*)d_in[0];          // pred_coords [b,n,3]
    const float* tc = (const float*)d_in[1];          // true_coords [b,n,3]
    const float* pf = (const float*)d_in[2];          // pred_frames [b,n,3,3]
    const float* tf = (const float*)d_in[3];          // true_frames [b,n,3,3]
    const int*   mask = (const int*)d_in[4];          // mask [b,n] (bool -> int32)
    int bn = in_sizes[4];                              // b*n
    int n  = (int)((long long)out_size / (long long)bn);
    int b  = bn / n;

    precompute_kernel<<<(bn + 127) / 128, 128>>>(pc, tc, pf, tf, mask, bn);
    dim3 grid((n + JT - 1) / JT, (n + IT - 1) / IT, b);
    pair_kernel<<<grid, JT>>>((float*)d_out, n);
}

// round 3
// speedup vs baseline: 1.0933x; 1.0933x over previous
#include <cuda_runtime.h>

// ---------------------------------------------------------------------------
// ComputeAlignmentError on GB300 (sm_103a).
// err[b,i,j] = || T_pred(i,j,:) - T_true(i,j,:) + 1e-8 ||_2 * mask[i]*mask[j]
// Factorized per-j constants + per-i coords. Pair kernel uses packed
// fma.rn.f32x2 (Blackwell f32x2 pipe) to produce TWO i-rows per iteration.
// mask arrives as int32 (bool promoted by harness).
// ---------------------------------------------------------------------------

#define MAX_BN 8192
__device__ float4 g_jc[MAX_BN * 6];   // per-frame: Ep(9), -Et(9), cc(3), mask
__device__ float4 g_ic[MAX_BN * 2];   // per-point: cp(3), mask | ct(3), 0

struct V3 { float x, y, z; };
__device__ __forceinline__ V3 v3(float x, float y, float z) { V3 v; v.x = x; v.y = y; v.z = z; return v; }
__device__ __forceinline__ V3 vsub(V3 a, V3 b) { return v3(a.x - b.x, a.y - b.y, a.z - b.z); }
__device__ __forceinline__ V3 vadd(V3 a, V3 b) { return v3(a.x + b.x, a.y + b.y, a.z + b.z); }
__device__ __forceinline__ float dot3(V3 a, V3 b) { return a.x * b.x + a.y * b.y + a.z * b.z; }
__device__ __forceinline__ V3 vnrm(V3 a) {
    float nn = sqrtf(dot3(a, a));
    float inv = 1.0f / fmaxf(nn, 1e-8f);
    return v3(a.x * inv, a.y * inv, a.z * inv);
}
__device__ __forceinline__ V3 vcross(V3 a, V3 b) {
    return v3(a.y * b.z - a.z * b.y,
              a.z * b.x - a.x * b.z,
              a.x * b.y - a.y * b.x);
}

__device__ __forceinline__ void frame_basis(const float* __restrict__ F,
                                            V3& o, V3& e1, V3& e2, V3& e3) {
    V3 a = v3(F[0], F[3], F[6]);
    V3 b = v3(F[1], F[4], F[7]);
    V3 c = v3(F[2], F[5], F[8]);
    V3 w1 = vnrm(vsub(a, b));
    V3 w2 = vnrm(vsub(c, b));
    e1 = vnrm(vadd(w1, w2));
    e2 = vnrm(vsub(w2, w1));
    e3 = vcross(e1, e2);
    o = b;
}

__global__ void precompute_kernel(const float* __restrict__ pc, const float* __restrict__ tc,
                                  const float* __restrict__ pf, const float* __restrict__ tf,
                                  const int* __restrict__ mask, int bn) {
    int t = blockIdx.x * blockDim.x + threadIdx.x;
    if (t >= bn) return;
    V3 op, p1, p2, p3, ot, t1, t2, t3;
    frame_basis(pf + (size_t)t * 9, op, p1, p2, p3);
    frame_basis(tf + (size_t)t * 9, ot, t1, t2, t3);
    float mf = (mask[t] != 0) ? 1.0f : 0.0f;
    const float eps = 1e-8f;
    float cc0 = eps - dot3(p1, op) + dot3(t1, ot);
    float cc1 = eps - dot3(p2, op) + dot3(t2, ot);
    float cc2 = eps - dot3(p3, op) + dot3(t3, ot);
    float4* jp = g_jc + (size_t)t * 6;
    jp[0] = make_float4(p1.x,  p1.y,  p1.z,  p2.x);
    jp[1] = make_float4(p2.y,  p2.z,  p3.x,  p3.y);
    jp[2] = make_float4(p3.z, -t1.x, -t1.y, -t1.z);
    jp[3] = make_float4(-t2.x, -t2.y, -t2.z, -t3.x);
    jp[4] = make_float4(-t3.y, -t3.z,  cc0,  cc1);
    jp[5] = make_float4(cc2,   mf,    0.0f,  0.0f);
    const float* cpp = pc + (size_t)t * 3;
    const float* ctp = tc + (size_t)t * 3;
    g_ic[(size_t)t * 2 + 0] = make_float4(cpp[0], cpp[1], cpp[2], mf);
    g_ic[(size_t)t * 2 + 1] = make_float4(ctp[0], ctp[1], ctp[2], 0.0f);
}

// ---- packed f32x2 helpers (Blackwell) ----
typedef unsigned long long ull;
__device__ __forceinline__ ull pk2(float lo, float hi) {
    ull r; asm("mov.b64 %0, {%1, %2};" : "=l"(r) : "f"(lo), "f"(hi)); return r;
}
__device__ __forceinline__ void unpk2(ull v, float& lo, float& hi) {
    asm("mov.b64 {%0, %1}, %2;" : "=f"(lo), "=f"(hi) : "l"(v));
}
__device__ __forceinline__ ull fma2(ull a, ull b, ull c) {
    ull d; asm("fma.rn.f32x2 %0, %1, %2, %3;" : "=l"(d) : "l"(a), "l"(b), "l"(c)); return d;
}
__device__ __forceinline__ ull mul2(ull a, ull b) {
    ull d; asm("mul.rn.f32x2 %0, %1, %2;" : "=l"(d) : "l"(a), "l"(b)); return d;
}
__device__ __forceinline__ float sqrt_approx(float s) {
    float r; asm("sqrt.approx.f32 %0, %1;" : "=f"(r) : "f"(s)); return r;
}

#define JT 128   // j-tile = blockDim.x (lane-major -> coalesced stores)
#define IT 64    // i-tile (SoA in smem); 2*IT <= JT for 1-load staging

__global__ void __launch_bounds__(JT) pair_kernel(float* __restrict__ out, int n) {
    // SoA i-tile: packed-pair reads via LDS.64 broadcast
    __shared__ __align__(16) float s_px[IT], s_py[IT], s_pz[IT];
    __shared__ __align__(16) float s_tx[IT], s_ty[IT], s_tz[IT];
    __shared__ __align__(16) float s_mi[IT];

    int bb    = blockIdx.z;
    int j     = blockIdx.x * JT + threadIdx.x;
    int ibase = blockIdx.y * IT;
    int base  = bb * n;
    int iend  = min(IT, n - ibase);

    // stage i-tile (one float4 per thread; 2*iend <= 128 = JT)
    int k = threadIdx.x;
    if (k < 2 * iend) {
        float4 f = g_ic[(size_t)(base + ibase) * 2 + k];
        int p = k >> 1;
        if (k & 1) { s_tx[p] = f.x; s_ty[p] = f.y; s_tz[p] = f.z; }
        else       { s_px[p] = f.x; s_py[p] = f.y; s_pz[p] = f.z; s_mi[p] = f.w; }
    }

    bool jok = j < n;
    const float4* jp = g_jc + (size_t)(base + (jok ? j : 0)) * 6;
    float4 q0 = jp[0], q1 = jp[1], q2 = jp[2], q3 = jp[3], q4 = jp[4], q5 = jp[5];
    // replicate j-constants into packed regs (once per thread)
    ull EP1X = pk2(q0.x, q0.x), EP1Y = pk2(q0.y, q0.y), EP1Z = pk2(q0.z, q0.z);
    ull EP2X = pk2(q0.w, q0.w), EP2Y = pk2(q1.x, q1.x), EP2Z = pk2(q1.y, q1.y);
    ull EP3X = pk2(q1.z, q1.z), EP3Y = pk2(q1.w, q1.w), EP3Z = pk2(q2.x, q2.x);
    ull MT1X = pk2(q2.y, q2.y), MT1Y = pk2(q2.z, q2.z), MT1Z = pk2(q2.w, q2.w);
    ull MT2X = pk2(q3.x, q3.x), MT2Y = pk2(q3.y, q3.y), MT2Z = pk2(q3.z, q3.z);
    ull MT3X = pk2(q3.w, q3.w), MT3Y = pk2(q4.x, q4.x), MT3Z = pk2(q4.y, q4.y);
    ull CC0  = pk2(q4.z, q4.z), CC1  = pk2(q4.w, q4.w), CC2  = pk2(q5.x, q5.x);
    ull MJ2  = pk2(q5.y, q5.y);
    __syncthreads();

    const ull* Px = (const ull*)s_px; const ull* Py = (const ull*)s_py;
    const ull* Pz = (const ull*)s_pz; const ull* Tx = (const ull*)s_tx;
    const ull* Ty = (const ull*)s_ty; const ull* Tz = (const ull*)s_tz;
    const ull* Mi = (const ull*)s_mi;

    float* orow = out + (size_t)(base + ibase) * n + j;
    long long nn = n;
    int npair = iend >> 1;
    #pragma unroll 2
    for (int t = 0; t < npair; ++t) {
        ull Ax = Px[t], Ay = Py[t], Az = Pz[t];
        ull Bx = Tx[t], By = Ty[t], Bz = Tz[t];
        ull x0 = fma2(EP1X, Ax, fma2(EP1Y, Ay, fma2(EP1Z, Az,
                 fma2(MT1X, Bx, fma2(MT1Y, By, fma2(MT1Z, Bz, CC0))))));
        ull x1 = fma2(EP2X, Ax, fma2(EP2Y, Ay, fma2(EP2Z, Az,
                 fma2(MT2X, Bx, fma2(MT2Y, By, fma2(MT2Z, Bz, CC1))))));
        ull x2 = fma2(EP3X, Ax, fma2(EP3Y, Ay, fma2(EP3Z, Az,
                 fma2(MT3X, Bx, fma2(MT3Y, By, fma2(MT3Z, Bz, CC2))))));
        ull s2 = fma2(x0, x0, fma2(x1, x1, mul2(x2, x2)));
        ull m2 = mul2(Mi[t], MJ2);
        float slo, shi, mlo, mhi;
        unpk2(s2, slo, shi);
        unpk2(m2, mlo, mhi);
        float rlo = sqrt_approx(slo) * mlo;
        float rhi = sqrt_approx(shi) * mhi;
        if (jok) { orow[0] = rlo; orow[nn] = rhi; }
        orow += 2 * nn;
    }
    // odd tail
    if (iend & 1) {
        int it = iend - 1;
        float Ax = s_px[it], Ay = s_py[it], Az = s_pz[it];
        float Bx = s_tx[it], By = s_ty[it], Bz = s_tz[it];
        float mi = s_mi[it];
        float c0, c1, c2, mj;
        unpk2(CC0, c0, c0); unpk2(CC1, c1, c1); unpk2(CC2, c2, c2); unpk2(MJ2, mj, mj);
        float x0 = fmaf(q0.x, Ax, fmaf(q0.y, Ay, fmaf(q0.z, Az,
                   fmaf(q2.y, Bx, fmaf(q2.z, By, fmaf(q2.w, Bz, c0))))));
        float x1 = fmaf(q0.w, Ax, fmaf(q1.x, Ay, fmaf(q1.y, Az,
                   fmaf(q3.x, Bx, fmaf(q3.y, By, fmaf(q3.z, Bz, c1))))));
        float x2 = fmaf(q1.z, Ax, fmaf(q1.w, Ay, fmaf(q2.x, Az,
                   fmaf(q3.w, Bx, fmaf(q4.x, By, fmaf(q4.y, Bz, c2))))));
        float s = fmaf(x0, x0, fmaf(x1, x1, x2 * x2));
        float r = sqrt_approx(s) * mi * mj;
        if (jok) orow[0] = r;
    }
}

extern "C" void kernel_launch(void* const* d_in, const int* in_sizes, int n_in,
                              void* d_out, int out_size) {
    const float* pc = (const float*)d_in[0];
    const float* tc = (const float*)d_in[1];
    const float* pf = (const float*)d_in[2];
    const float* tf = (const float*)d_in[3];
    const int*   mask = (const int*)d_in[4];
    int bn = in_sizes[4];
    int n  = (int)((long long)out_size / (long long)bn);
    int b  = bn / n;

    precompute_kernel<<<(bn + 127) / 128, 128>>>(pc, tc, pf, tf, mask, bn);
    dim3 grid((n + JT - 1) / JT, (n + IT - 1) / IT, b);
    pair_kernel<<<grid, JT>>>((float*)d_out, n);
}

// round 7
// speedup vs baseline: 1.2448x; 1.1385x over previous
#include <cuda_runtime.h>

// ---------------------------------------------------------------------------
// ComputeAlignmentError on GB300 (sm_103a).
// err[b,i,j] = || T_pred(i,j,:) - T_true(i,j,:) + 1e-8 ||_2 * mask[i]*mask[j]
// Factorized per-j constants + per-i coords. Pair kernel uses packed
// fma.rn.f32x2 producing TWO i-rows per iteration.
// R4: IT=32 (2048 blocks, ~55 warps/SM) + unroll 4 to fix latency binding
// (R3: issue=49%, occ=32%).
// ---------------------------------------------------------------------------

#define MAX_BN 8192
__device__ float4 g_jc[MAX_BN * 6];   // per-frame: Ep(9), -Et(9), cc(3), mask
__device__ float4 g_ic[MAX_BN * 2];   // per-point: cp(3), mask | ct(3), 0

struct V3 { float x, y, z; };
__device__ __forceinline__ V3 v3(float x, float y, float z) { V3 v; v.x = x; v.y = y; v.z = z; return v; }
__device__ __forceinline__ V3 vsub(V3 a, V3 b) { return v3(a.x - b.x, a.y - b.y, a.z - b.z); }
__device__ __forceinline__ V3 vadd(V3 a, V3 b) { return v3(a.x + b.x, a.y + b.y, a.z + b.z); }
__device__ __forceinline__ float dot3(V3 a, V3 b) { return a.x * b.x + a.y * b.y + a.z * b.z; }
__device__ __forceinline__ V3 vnrm(V3 a) {
    float nn = sqrtf(dot3(a, a));
    float inv = 1.0f / fmaxf(nn, 1e-8f);
    return v3(a.x * inv, a.y * inv, a.z * inv);
}
__device__ __forceinline__ V3 vcross(V3 a, V3 b) {
    return v3(a.y * b.z - a.z * b.y,
              a.z * b.x - a.x * b.z,
              a.x * b.y - a.y * b.x);
}

__device__ __forceinline__ void frame_basis(const float* __restrict__ F,
                                            V3& o, V3& e1, V3& e2, V3& e3) {
    V3 a = v3(F[0], F[3], F[6]);
    V3 b = v3(F[1], F[4], F[7]);
    V3 c = v3(F[2], F[5], F[8]);
    V3 w1 = vnrm(vsub(a, b));
    V3 w2 = vnrm(vsub(c, b));
    e1 = vnrm(vadd(w1, w2));
    e2 = vnrm(vsub(w2, w1));
    e3 = vcross(e1, e2);
    o = b;
}

__global__ void precompute_kernel(const float* __restrict__ pc, const float* __restrict__ tc,
                                  const float* __restrict__ pf, const float* __restrict__ tf,
                                  const int* __restrict__ mask, int bn) {
    int t = blockIdx.x * blockDim.x + threadIdx.x;
    if (t >= bn) return;
    V3 op, p1, p2, p3, ot, t1, t2, t3;
    frame_basis(pf + (size_t)t * 9, op, p1, p2, p3);
    frame_basis(tf + (size_t)t * 9, ot, t1, t2, t3);
    float mf = (mask[t] != 0) ? 1.0f : 0.0f;
    const float eps = 1e-8f;
    float cc0 = eps - dot3(p1, op) + dot3(t1, ot);
    float cc1 = eps - dot3(p2, op) + dot3(t2, ot);
    float cc2 = eps - dot3(p3, op) + dot3(t3, ot);
    float4* jp = g_jc + (size_t)t * 6;
    jp[0] = make_float4(p1.x,  p1.y,  p1.z,  p2.x);
    jp[1] = make_float4(p2.y,  p2.z,  p3.x,  p3.y);
    jp[2] = make_float4(p3.z, -t1.x, -t1.y, -t1.z);
    jp[3] = make_float4(-t2.x, -t2.y, -t2.z, -t3.x);
    jp[4] = make_float4(-t3.y, -t3.z,  cc0,  cc1);
    jp[5] = make_float4(cc2,   mf,    0.0f,  0.0f);
    const float* cpp = pc + (size_t)t * 3;
    const float* ctp = tc + (size_t)t * 3;
    g_ic[(size_t)t * 2 + 0] = make_float4(cpp[0], cpp[1], cpp[2], mf);
    g_ic[(size_t)t * 2 + 1] = make_float4(ctp[0], ctp[1], ctp[2], 0.0f);
}

// ---- packed f32x2 helpers (Blackwell) ----
typedef unsigned long long ull;
__device__ __forceinline__ ull pk2(float lo, float hi) {
    ull r; asm("mov.b64 %0, {%1, %2};" : "=l"(r) : "f"(lo), "f"(hi)); return r;
}
__device__ __forceinline__ void unpk2(ull v, float& lo, float& hi) {
    asm("mov.b64 {%0, %1}, %2;" : "=f"(lo), "=f"(hi) : "l"(v));
}
__device__ __forceinline__ ull fma2(ull a, ull b, ull c) {
    ull d; asm("fma.rn.f32x2 %0, %1, %2, %3;" : "=l"(d) : "l"(a), "l"(b), "l"(c)); return d;
}
__device__ __forceinline__ ull mul2(ull a, ull b) {
    ull d; asm("mul.rn.f32x2 %0, %1, %2;" : "=l"(d) : "l"(a), "l"(b)); return d;
}
__device__ __forceinline__ float sqrt_approx(float s) {
    float r; asm("sqrt.approx.f32 %0, %1;" : "=f"(r) : "f"(s)); return r;
}

#define JT 128   // j-tile = blockDim.x (lane-major -> coalesced stores)
#define IT 32    // i-tile (SoA in smem); small tile -> 2048 blocks, ~55 warps/SM

__global__ void __launch_bounds__(JT) pair_kernel(float* __restrict__ out, int n) {
    __shared__ __align__(16) float s_px[IT], s_py[IT], s_pz[IT];
    __shared__ __align__(16) float s_tx[IT], s_ty[IT], s_tz[IT];
    __shared__ __align__(16) float s_mi[IT];

    int bb    = blockIdx.z;
    int j     = blockIdx.x * JT + threadIdx.x;
    int ibase = blockIdx.y * IT;
    int base  = bb * n;
    int iend  = min(IT, n - ibase);

    // stage i-tile (one float4 per thread; 2*iend <= 64 <= 128 = JT)
    int k = threadIdx.x;
    if (k < 2 * iend) {
        float4 f = g_ic[(size_t)(base + ibase) * 2 + k];
        int p = k >> 1;
        if (k & 1) { s_tx[p] = f.x; s_ty[p] = f.y; s_tz[p] = f.z; }
        else       { s_px[p] = f.x; s_py[p] = f.y; s_pz[p] = f.z; s_mi[p] = f.w; }
    }

    bool jok = j < n;
    const float4* jp = g_jc + (size_t)(base + (jok ? j : 0)) * 6;
    float4 q0 = jp[0], q1 = jp[1], q2 = jp[2], q3 = jp[3], q4 = jp[4], q5 = jp[5];
    ull EP1X = pk2(q0.x, q0.x), EP1Y = pk2(q0.y, q0.y), EP1Z = pk2(q0.z, q0.z);
    ull EP2X = pk2(q0.w, q0.w), EP2Y = pk2(q1.x, q1.x), EP2Z = pk2(q1.y, q1.y);
    ull EP3X = pk2(q1.z, q1.z), EP3Y = pk2(q1.w, q1.w), EP3Z = pk2(q2.x, q2.x);
    ull MT1X = pk2(q2.y, q2.y), MT1Y = pk2(q2.z, q2.z), MT1Z = pk2(q2.w, q2.w);
    ull MT2X = pk2(q3.x, q3.x), MT2Y = pk2(q3.y, q3.y), MT2Z = pk2(q3.z, q3.z);
    ull MT3X = pk2(q3.w, q3.w), MT3Y = pk2(q4.x, q4.x), MT3Z = pk2(q4.y, q4.y);
    ull CC0  = pk2(q4.z, q4.z), CC1  = pk2(q4.w, q4.w), CC2  = pk2(q5.x, q5.x);
    ull MJ2  = pk2(q5.y, q5.y);
    __syncthreads();

    const ull* Px = (const ull*)s_px; const ull* Py = (const ull*)s_py;
    const ull* Pz = (const ull*)s_pz; const ull* Tx = (const ull*)s_tx;
    const ull* Ty = (const ull*)s_ty; const ull* Tz = (const ull*)s_tz;
    const ull* Mi = (const ull*)s_mi;

    float* orow = out + (size_t)(base + ibase) * n + j;
    long long nn = n;
    int npair = iend >> 1;
    #pragma unroll 4
    for (int t = 0; t < npair; ++t) {
        ull Ax = Px[t], Ay = Py[t], Az = Pz[t];
        ull Bx = Tx[t], By = Ty[t], Bz = Tz[t];
        ull x0 = fma2(EP1X, Ax, fma2(EP1Y, Ay, fma2(EP1Z, Az,
                 fma2(MT1X, Bx, fma2(MT1Y, By, fma2(MT1Z, Bz, CC0))))));
        ull x1 = fma2(EP2X, Ax, fma2(EP2Y, Ay, fma2(EP2Z, Az,
                 fma2(MT2X, Bx, fma2(MT2Y, By, fma2(MT2Z, Bz, CC1))))));
        ull x2 = fma2(EP3X, Ax, fma2(EP3Y, Ay, fma2(EP3Z, Az,
                 fma2(MT3X, Bx, fma2(MT3Y, By, fma2(MT3Z, Bz, CC2))))));
        ull s2 = fma2(x0, x0, fma2(x1, x1, mul2(x2, x2)));
        ull m2 = mul2(Mi[t], MJ2);
        float slo, shi, mlo, mhi;
        unpk2(s2, slo, shi);
        unpk2(m2, mlo, mhi);
        float rlo = sqrt_approx(slo) * mlo;
        float rhi = sqrt_approx(shi) * mhi;
        if (jok) { orow[0] = rlo; orow[nn] = rhi; }
        orow += 2 * nn;
    }
    if (iend & 1) {
        int it = iend - 1;
        float Ax = s_px[it], Ay = s_py[it], Az = s_pz[it];
        float Bx = s_tx[it], By = s_ty[it], Bz = s_tz[it];
        float mi = s_mi[it];
        float c0, c1, c2, mj;
        unpk2(CC0, c0, c0); unpk2(CC1, c1, c1); unpk2(CC2, c2, c2); unpk2(MJ2, mj, mj);
        float x0 = fmaf(q0.x, Ax, fmaf(q0.y, Ay, fmaf(q0.z, Az,
                   fmaf(q2.y, Bx, fmaf(q2.z, By, fmaf(q2.w, Bz, c0))))));
        float x1 = fmaf(q0.w, Ax, fmaf(q1.x, Ay, fmaf(q1.y, Az,
                   fmaf(q3.x, Bx, fmaf(q3.y, By, fmaf(q3.z, Bz, c1))))));
        float x2 = fmaf(q1.z, Ax, fmaf(q1.w, Ay, fmaf(q2.x, Az,
                   fmaf(q3.w, Bx, fmaf(q4.x, By, fmaf(q4.y, Bz, c2))))));
        float s = fmaf(x0, x0, fmaf(x1, x1, x2 * x2));
        float r = sqrt_approx(s) * mi * mj;
        if (jok) orow[0] = r;
    }
}

extern "C" void kernel_launch(void* const* d_in, const int* in_sizes, int n_in,
                              void* d_out, int out_size) {
    const float* pc = (const float*)d_in[0];
    const float* tc = (const float*)d_in[1];
    const float* pf = (const float*)d_in[2];
    const float* tf = (const float*)d_in[3];
    const int*   mask = (const int*)d_in[4];
    int bn = in_sizes[4];
    int n  = (int)((long long)out_size / (long long)bn);
    int b  = bn / n;

    precompute_kernel<<<(bn + 127) / 128, 128>>>(pc, tc, pf, tf, mask, bn);
    dim3 grid((n + JT - 1) / JT, (n + IT - 1) / IT, b);
    pair_kernel<<<grid, JT>>>((float*)d_out, n);
}